// round 13
// baseline (speedup 1.0000x reference)
#include <cuda_runtime.h>
#include <cuda_bf16.h>
#include <cstdint>
#include <cstddef>

#define NB   2
#define NN   3072
#define CC   512
#define MM   (NB * NN)      // 6144
#define HH   8
#define DD   64
#define KLOG 1536           // logical split-K: A=[hi|lo|hi], B=[hi|hi|lo]
#define KA   1024           // physical storage: [hi|lo]
#define NQKV 1536

// ---------------------------------------------------------------------------
// Device scratch
// ---------------------------------------------------------------------------
__device__ __align__(1024) __nv_bfloat16 g_A[(size_t)MM * KA];      // split activations [hi|lo]
__device__ __align__(1024) __nv_bfloat16 g_Bqkv[(size_t)NQKV * KA]; // [Wq;Wk;Wv] split [hi|lo]
__device__ __align__(1024) __nv_bfloat16 g_Bout[(size_t)CC * KA];   // Wp split [hi|lo]
__device__ __align__(16)   float g_qkv[(size_t)MM * NQKV];          // q|k|v fp32

// ---------------------------------------------------------------------------
// helpers
// ---------------------------------------------------------------------------
__device__ __forceinline__ uint32_t smem_u32(const void* p) {
    uint32_t a;
    asm("{ .reg .u64 t; cvta.to.shared.u64 t, %1; cvt.u32.u64 %0, t; }" : "=r"(a) : "l"(p));
    return a;
}

#define CP16(dst_u32, src_ptr) \
    asm volatile("cp.async.cg.shared.global [%0], [%1], 16;" :: "r"(dst_u32), "l"(src_ptr))
#define CP_COMMIT()  asm volatile("cp.async.commit_group;" ::: "memory")
#define CP_WAITG(n)  asm volatile("cp.async.wait_group %0;" :: "n"(n) : "memory")

#define LDSM_X4(r0, r1, r2, r3, addr) \
    asm volatile("ldmatrix.sync.aligned.m8n8.x4.shared.b16 {%0,%1,%2,%3}, [%4];" \
                 : "=r"(r0), "=r"(r1), "=r"(r2), "=r"(r3) : "r"(addr))

__device__ __forceinline__ void mma16816(float* c, const uint32_t* a, const uint32_t* b) {
    asm volatile(
        "mma.sync.aligned.m16n8k16.row.col.f32.bf16.bf16.f32 "
        "{%0,%1,%2,%3}, {%4,%5,%6,%7}, {%8,%9}, {%0,%1,%2,%3};"
        : "+f"(c[0]), "+f"(c[1]), "+f"(c[2]), "+f"(c[3])
        : "r"(a[0]), "r"(a[1]), "r"(a[2]), "r"(a[3]), "r"(b[0]), "r"(b[1]));
}

// ---------------------------------------------------------------------------
// Hi/lo splitters -> physical [hi(512) | lo(512)] rows of KA=1024.
// Logical GEMM K expansion happens via chunk remapping in gemm_hmma.
// ---------------------------------------------------------------------------
__device__ __forceinline__ void split_core(const float* __restrict__ in, int idx,
                                           int& r, int& c, uint2& H, uint2& L)
{
    r = idx >> 7;
    c = (idx & 127) << 2;
    float4 v = *reinterpret_cast<const float4*>(in + (size_t)r * CC + c);
    float f[4] = {v.x, v.y, v.z, v.w};
    uint32_t h[2], l[2];
    #pragma unroll
    for (int i = 0; i < 2; i++) {
        __nv_bfloat16 h0 = __float2bfloat16(f[2*i]);
        __nv_bfloat16 h1 = __float2bfloat16(f[2*i + 1]);
        __nv_bfloat16 l0 = __float2bfloat16(f[2*i]     - __bfloat162float(h0));
        __nv_bfloat16 l1 = __float2bfloat16(f[2*i + 1] - __bfloat162float(h1));
        h[i] = (uint32_t)__bfloat16_as_ushort(h0) | ((uint32_t)__bfloat16_as_ushort(h1) << 16);
        l[i] = (uint32_t)__bfloat16_as_ushort(l0) | ((uint32_t)__bfloat16_as_ushort(l1) << 16);
    }
    H = make_uint2(h[0], h[1]);
    L = make_uint2(l[0], l[1]);
}

__global__ void split2(const float* __restrict__ in, __nv_bfloat16* __restrict__ out, int rows)
{
    int idx = blockIdx.x * 256 + threadIdx.x;
    if (idx >= rows * 128) return;
    int r, c; uint2 H, L;
    split_core(in, idx, r, c, H, L);
    size_t base = (size_t)r * KA;
    *reinterpret_cast<uint2*>(out + base + c)       = H;
    *reinterpret_cast<uint2*>(out + base + 512 + c) = L;
}

__global__ void split2_w4(const float* __restrict__ Wq, const float* __restrict__ Wk,
                          const float* __restrict__ Wv, const float* __restrict__ Wp,
                          __nv_bfloat16* __restrict__ Bq, __nv_bfloat16* __restrict__ Bo)
{
    const int which = blockIdx.y;
    const float* src = (which == 0) ? Wq : (which == 1) ? Wk : (which == 2) ? Wv : Wp;
    __nv_bfloat16* dst = (which == 0) ? Bq
                       : (which == 1) ? Bq + (size_t)512 * KA
                       : (which == 2) ? Bq + (size_t)1024 * KA
                       : Bo;
    int idx = blockIdx.x * 256 + threadIdx.x;
    if (idx >= CC * 128) return;
    int r, c; uint2 H, L;
    split_core(src, idx, r, c, H, L);
    size_t base = (size_t)r * KA;
    *reinterpret_cast<uint2*>(dst + base + c)       = H;
    *reinterpret_cast<uint2*>(dst + base + 512 + c) = L;
}

// ---------------------------------------------------------------------------
// HMMA GEMM, logical K=1536 over physical [hi|lo] (KA=1024):
//   A chunks: kt 0-15 hi, 16-31 lo, 32-47 hi  -> ka = kt<32 ? kt : kt-32
//   B chunks: kt 0-15 hi, 16-31 hi, 32-47 lo  -> kb = kt<16 ? kt : kt-16
// BM=128: 2 CTAs/SM (QKV).  BM=64: 3 CTAs/SM (out proj, one full wave).
// 4-stage cp.async, ldmatrix, single barrier per iteration.
// ---------------------------------------------------------------------------
#define BK      32
#define PAD     40
#define STAGES  4
#define NKCH    (KLOG / BK)            // 48

template<int BM>
__global__ void __launch_bounds__(256, BM == 128 ? 2 : 3)
gemm_hmma(const __nv_bfloat16* __restrict__ Ag,
          const __nv_bfloat16* __restrict__ Bg,
          float* __restrict__ C, int ldc, const float* __restrict__ bias)
{
    constexpr int MI      = BM / 32;
    constexpr int TILEA   = BM * PAD;
    constexpr int TILEB   = 128 * PAD;

    extern __shared__ __align__(16) char smem[];
    const uint32_t sbase = smem_u32(smem);

    const int tid  = threadIdx.x;
    const int wid  = tid >> 5;
    const int lane = tid & 31;
    const int g    = lane >> 2;
    const int tig  = lane & 3;

    const int bm = blockIdx.y * BM;
    const int bn = blockIdx.x * 128;
    const int wm = (wid & 1) * (BM / 2);
    const int wn = (wid >> 1) * 32;

    auto load_stage = [&](int kt, int s) {
        const int ka = (kt < 32) ? kt : kt - 32;
        const int kb = (kt < 16) ? kt : kt - 16;
        const uint32_t abase = sbase + (uint32_t)(s * TILEA) * 2;
        const uint32_t bbase = sbase + (uint32_t)(STAGES * TILEA + s * TILEB) * 2;
        if constexpr (BM == 128) {
            const int r0 = tid >> 1;
            const int c0 = (tid & 1) * 16;
            const __nv_bfloat16* ap = Ag + (size_t)(bm + r0) * KA + ka * BK + c0;
            const uint32_t aoff = abase + (uint32_t)(r0 * PAD + c0) * 2;
            CP16(aoff,      ap);
            CP16(aoff + 16, ap + 8);
        } else {
            const int r0 = tid >> 2;
            const int c0 = (tid & 3) * 8;
            const __nv_bfloat16* ap = Ag + (size_t)(bm + r0) * KA + ka * BK + c0;
            CP16(abase + (uint32_t)(r0 * PAD + c0) * 2, ap);
        }
        {
            const int r0 = tid >> 1;
            const int c0 = (tid & 1) * 16;
            const __nv_bfloat16* bp = Bg + (size_t)(bn + r0) * KA + kb * BK + c0;
            const uint32_t boff = bbase + (uint32_t)(r0 * PAD + c0) * 2;
            CP16(boff,      bp);
            CP16(boff + 16, bp + 8);
        }
    };

    const uint32_t a_off = (uint32_t)((wm + (lane & 15)) * PAD + (lane >> 4) * 8) * 2;
    const uint32_t b_off = (uint32_t)((wn + (lane >> 4) * 8 + (lane & 7)) * PAD
                                      + ((lane >> 3) & 1) * 8) * 2;

    float acc[MI][4][4] = {};

    load_stage(0, 0); CP_COMMIT();
    load_stage(1, 1); CP_COMMIT();
    load_stage(2, 2); CP_COMMIT();

    for (int kt = 0; kt < NKCH; kt++) {
        CP_WAITG(2);
        __syncthreads();

        const int nk = kt + STAGES - 1;
        if (nk < NKCH) load_stage(nk, nk & 3);
        CP_COMMIT();

        const uint32_t at = sbase + (uint32_t)((kt & 3) * TILEA) * 2 + a_off;
        const uint32_t bt = sbase + (uint32_t)(STAGES * TILEA + (kt & 3) * TILEB) * 2 + b_off;

        #pragma unroll
        for (int kk = 0; kk < BK; kk += 16) {
            uint32_t af[MI][4], bf[4][2];
            #pragma unroll
            for (int mi = 0; mi < MI; mi++)
                LDSM_X4(af[mi][0], af[mi][1], af[mi][2], af[mi][3],
                        at + (uint32_t)(mi * 16 * PAD + kk) * 2);
            #pragma unroll
            for (int np = 0; np < 2; np++)
                LDSM_X4(bf[2*np][0], bf[2*np][1], bf[2*np+1][0], bf[2*np+1][1],
                        bt + (uint32_t)(np * 16 * PAD + kk) * 2);
            #pragma unroll
            for (int mi = 0; mi < MI; mi++)
                #pragma unroll
                for (int ni = 0; ni < 4; ni++)
                    mma16816(acc[mi][ni], af[mi], bf[ni]);
        }
    }

    #pragma unroll
    for (int mi = 0; mi < MI; mi++) {
        const int row0 = bm + wm + mi * 16 + g;
        #pragma unroll
        for (int ni = 0; ni < 4; ni++) {
            const int col = bn + wn + ni * 8 + tig * 2;
            float b0 = 0.f, b1 = 0.f;
            if (bias) { b0 = bias[col]; b1 = bias[col + 1]; }
            float2 lo = make_float2(acc[mi][ni][0] + b0, acc[mi][ni][1] + b1);
            float2 hi = make_float2(acc[mi][ni][2] + b0, acc[mi][ni][3] + b1);
            *reinterpret_cast<float2*>(C + (size_t)row0 * ldc + col)       = lo;
            *reinterpret_cast<float2*>(C + (size_t)(row0 + 8) * ldc + col) = hi;
        }
    }
}

// ---------------------------------------------------------------------------
// Tiled sparse triplane attention: key-major warps, V-from-L2, K prefetch,
// key-major probs exchange P[64][PROW] (g0 PV prob reads = 1 LDS.128).
// Union region Sh (1280 floats) time-multiplexes: Q stage -> scores/probs P
// -> partial-output exchange.  Fused [hi|lo] output split.  3 CTAs/SM.
// ---------------------------------------------------------------------------
#define KROW 68         // K buffer row stride (floats)
#define PROW 20         // P row stride (floats)

__global__ void __launch_bounds__(256, 3)
attn_tile(const float* __restrict__ qkv, __nv_bfloat16* __restrict__ Aout)
{
    extern __shared__ __align__(16) float sm[];
    float* Ks = sm;                            // [256][KROW]  K only
    float* Sh = sm + 256 * KROW;               // union: Q[16][64] / P[64][PROW] / O[16][64]
    const uint32_t ks_base = smem_u32(Ks);
    const uint32_t sh_base = smem_u32(Sh);

    const int x  = blockIdx.x;                 // 0..383
    const int b  = x / 192;
    const int r0 = x % 192;
    const int p  = r0 >> 6;
    const int t0 = r0 & 63;
    const int i0 = (t0 >> 3) << 2;
    const int j0 = (t0 & 7) << 2;

    const int tid  = threadIdx.x;
    const int wid  = tid >> 5;
    const int lane = tid & 31;

    const float* Bq = qkv + (size_t)b * NN * NQKV;

    // global row for buffer row rr (computed inline; no smem table)
    auto grow = [&](int rr) -> int {
        const int rl = rr & 127;
        if (p == 0)
            return (rr < 128) ? (1024 + 32 * i0 + rl) : (2048 + 32 * j0 + rl);
        else if (p == 1)
            return (rr < 128) ? (32 * i0 + rl)
                              : (2048 + 32 * (rl & 31) + j0 + (rl >> 5));
        else
            return (rr < 128) ? (32 * (rl & 31) + i0 + (rl >> 5))
                              : (1024 + 32 * (rl & 31) + j0 + (rl >> 5));
    };

    const bool g0     = (wid < 4);
    const int  grp    = g0 ? wid : (wid - 4);
    const int  krow0  = g0 ? (grp * 32) : (128 + grp * 32);
    const int  c4t    = tid & 15;
    const int  myGrow = grow(krow0 + lane);

    auto load_K = [&](int h) {
        #pragma unroll
        for (int it = 0; it < 16; it++) {
            const int rr = it * 16 + (tid >> 4);
            const float* src = Bq + (size_t)grow(rr) * NQKV + 512 + h * DD + c4t * 4;
            CP16(ks_base + (uint32_t)(rr * KROW + c4t * 4) * 4, src);
        }
    };

    load_K(0); CP_COMMIT();

    for (int h = 0; h < HH; h++) {
        // ---- Q(h) into union region (previous oex fully read at S8) ----
        {
            const int qr = tid >> 4;
            const int n  = (p << 10) + (i0 + (qr >> 2)) * 32 + (j0 + (qr & 3));
            CP16(sh_base + (uint32_t)(qr * 64 + c4t * 4) * 4,
                 Bq + (size_t)n * NQKV + h * DD + c4t * 4);
        }
        CP_COMMIT(); CP_WAITG(0);
        __syncthreads();                               // S1: K(h) + Q(h) ready

        // ---- QK: lane = key, 4 queries per warp, K row read ONCE ----
        float s[4] = {0.f, 0.f, 0.f, 0.f};
        {
            const float4* Krow = reinterpret_cast<const float4*>(Ks + (krow0 + lane) * KROW);
            #pragma unroll
            for (int d4 = 0; d4 < 16; d4++) {
                const float4 kv = Krow[d4];
                #pragma unroll
                for (int qq = 0; qq < 4; qq++) {
                    const int q = g0 ? (grp * 4 + qq) : (qq * 4 + grp);
                    const float4 qv = *reinterpret_cast<const float4*>(Sh + q * 64 + d4 * 4);
                    s[qq] += qv.x * kv.x + qv.y * kv.y + qv.z * kv.z + qv.w * kv.w;
                }
            }
        }
        __syncthreads();                               // S2: K + Q reads done

        // ---- prefetch K(h+1) into the dead K buffer ----
        if (h + 1 < HH) load_K(h + 1);
        CP_COMMIT();

        // ---- scores -> P[key-slot][q] (over Q region) ----
        if (g0) {
            float4 sv = make_float4(s[0] * 0.125f, s[1] * 0.125f,
                                    s[2] * 0.125f, s[3] * 0.125f);
            *reinterpret_cast<float4*>(Sh + lane * PROW + grp * 4) = sv;
        } else {
            #pragma unroll
            for (int qq = 0; qq < 4; qq++)
                Sh[(32 + lane) * PROW + qq * 4 + grp] = s[qq] * 0.125f;
        }
        __syncthreads();                               // S3: scores visible

        // ---- softmax over column q: warp w -> queries 2w, 2w+1 ----
        #pragma unroll
        for (int qq = 0; qq < 2; qq++) {
            const int q = wid * 2 + qq;
            float s0 = Sh[lane * PROW + q];
            float s1 = Sh[(32 + lane) * PROW + q];
            float m = fmaxf(s0, s1);
            #pragma unroll
            for (int off = 16; off; off >>= 1)
                m = fmaxf(m, __shfl_xor_sync(0xffffffffu, m, off));
            const float e0 = __expf(s0 - m), e1 = __expf(s1 - m);
            float su = e0 + e1;
            #pragma unroll
            for (int off = 16; off; off >>= 1)
                su += __shfl_xor_sync(0xffffffffu, su, off);
            const float inv = 1.0f / su;
            Sh[lane * PROW + q]        = e0 * inv;
            Sh[(32 + lane) * PROW + q] = e1 * inv;
        }
        __syncthreads();                               // S4: probs visible

        // ---- PV: V from L2, lane = dim pair, V row read ONCE ----
        float o[4][2] = {};
        #pragma unroll
        for (int t = 0; t < 32; t++) {
            const int gr = __shfl_sync(0xffffffffu, myGrow, t);
            const float2 v2 = *reinterpret_cast<const float2*>(
                Bq + (size_t)gr * NQKV + 1024 + h * DD + 2 * lane);
            if (g0) {
                const float4 p4 = *reinterpret_cast<const float4*>(Sh + t * PROW + grp * 4);
                o[0][0] += p4.x * v2.x; o[0][1] += p4.x * v2.y;
                o[1][0] += p4.y * v2.x; o[1][1] += p4.y * v2.y;
                o[2][0] += p4.z * v2.x; o[2][1] += p4.z * v2.y;
                o[3][0] += p4.w * v2.x; o[3][1] += p4.w * v2.y;
            } else {
                #pragma unroll
                for (int qq = 0; qq < 4; qq++) {
                    const float pt = Sh[(32 + t) * PROW + qq * 4 + grp];
                    o[qq][0] += pt * v2.x;
                    o[qq][1] += pt * v2.y;
                }
            }
        }
        __syncthreads();                               // S5: prob reads done

        // ---- combine partials in O[q][64] (over P region) ----
        if (g0) {
            #pragma unroll
            for (int qq = 0; qq < 4; qq++) {
                const int q = grp * 4 + qq;
                *reinterpret_cast<float2*>(Sh + q * 64 + 2 * lane) =
                    make_float2(o[qq][0], o[qq][1]);
            }
        }
        __syncthreads();                               // S6: g0 partials visible
        if (!g0) {
            #pragma unroll
            for (int qq = 0; qq < 4; qq++) {
                const int q = qq * 4 + grp;
                float2 v = *reinterpret_cast<float2*>(Sh + q * 64 + 2 * lane);
                v.x += o[qq][0]; v.y += o[qq][1];
                *reinterpret_cast<float2*>(Sh + q * 64 + 2 * lane) = v;
            }
        }
        __syncthreads();                               // S7: sums visible

        // ---- output: fused [hi|lo] split write ----
        #pragma unroll
        for (int qq = 0; qq < 2; qq++) {
            const int q = wid * 2 + qq;
            const float2 ov = *reinterpret_cast<const float2*>(Sh + q * 64 + 2 * lane);
            const int n = (p << 10) + (i0 + (q >> 2)) * 32 + (j0 + (q & 3));
            const size_t ab = (size_t)(b * NN + n) * KA + h * DD;
            const __nv_bfloat16 h0 = __float2bfloat16(ov.x);
            const __nv_bfloat16 l0 = __float2bfloat16(ov.x - __bfloat162float(h0));
            const __nv_bfloat16 h1 = __float2bfloat16(ov.y);
            const __nv_bfloat16 l1 = __float2bfloat16(ov.y - __bfloat162float(h1));
            __nv_bfloat162 Hp; Hp.x = h0; Hp.y = h1;
            __nv_bfloat162 Lp; Lp.x = l0; Lp.y = l1;
            *reinterpret_cast<__nv_bfloat162*>(&Aout[ab + 2 * lane])       = Hp;
            *reinterpret_cast<__nv_bfloat162*>(&Aout[ab + 512 + 2 * lane]) = Lp;
        }
        __syncthreads();                               // S8: O reads done
    }
}

// ---------------------------------------------------------------------------
// Host side
// ---------------------------------------------------------------------------
extern "C" void kernel_launch(void* const* d_in, const int* in_sizes, int n_in,
                              void* d_out, int out_size)
{
    const float* x  = (const float*)d_in[0];
    const float* Wq = (const float*)d_in[1];
    const float* Wk = (const float*)d_in[2];
    const float* Wv = (const float*)d_in[3];
    const float* Wp = (const float*)d_in[4];
    const float* bp = (const float*)d_in[5];
    float* out = (float*)d_out;

    __nv_bfloat16 *A, *Bq, *Bo;
    float *qkv;
    cudaGetSymbolAddress((void**)&A,   g_A);
    cudaGetSymbolAddress((void**)&Bq,  g_Bqkv);
    cudaGetSymbolAddress((void**)&Bo,  g_Bout);
    cudaGetSymbolAddress((void**)&qkv, g_qkv);

    constexpr int SMEM_G128 = STAGES * (128 + 128) * PAD * 2;        // 81920
    constexpr int SMEM_G64  = STAGES * (64 + 128) * PAD * 2;         // 61440
    constexpr int SMEM_A    = (256 * KROW + 1280) * 4;               // 74752
    static bool s_attr = false;
    if (!s_attr) {
        cudaFuncSetAttribute(gemm_hmma<128>, cudaFuncAttributeMaxDynamicSharedMemorySize, SMEM_G128);
        cudaFuncSetAttribute(gemm_hmma<64>,  cudaFuncAttributeMaxDynamicSharedMemorySize, SMEM_G64);
        cudaFuncSetAttribute(attn_tile,      cudaFuncAttributeMaxDynamicSharedMemorySize, SMEM_A);
        s_attr = true;
    }

    // 1) hi/lo splits (compact [hi|lo] storage)
    split2<<<(MM * 128 + 255) / 256, 256>>>(x, A, MM);
    split2_w4<<<dim3((CC * 128 + 255) / 256, 4), 256>>>(Wq, Wk, Wv, Wp, Bq, Bo);

    // 2) fused QKV projection (logical K=1536 via chunk remap)
    gemm_hmma<128><<<dim3(NQKV / 128, MM / 128), 256, SMEM_G128>>>(A, Bq, qkv, NQKV, nullptr);

    // 3) tiled sparse attention (writes compact split A directly)
    attn_tile<<<NB * 3 * 64, 256, SMEM_A>>>(qkv, A);

    // 4) output projection (BM=64: one full wave)
    gemm_hmma<64><<<dim3(CC / 128, MM / 64), 256, SMEM_G64>>>(A, Bo, out, CC, bp);
}

// round 14
// speedup vs baseline: 1.0714x; 1.0714x over previous
#include <cuda_runtime.h>
#include <cuda_bf16.h>
#include <cstdint>
#include <cstddef>

#define NB   2
#define NN   3072
#define CC   512
#define MM   (NB * NN)      // 6144
#define HH   8
#define DD   64
#define KLOG 1536           // logical split-K: A=[hi|lo|hi], B=[hi|hi|lo]
#define KA   1024           // physical storage: [hi|lo]
#define NQKV 1536

// ---------------------------------------------------------------------------
// Device scratch
// ---------------------------------------------------------------------------
__device__ __align__(1024) __nv_bfloat16 g_A[(size_t)MM * KA];      // split activations [hi|lo]
__device__ __align__(1024) __nv_bfloat16 g_Bqkv[(size_t)NQKV * KA]; // [Wq;Wk;Wv] split [hi|lo]
__device__ __align__(1024) __nv_bfloat16 g_Bout[(size_t)CC * KA];   // Wp split [hi|lo]
__device__ __align__(16)   float g_qkv[(size_t)MM * NQKV];          // q|k|v fp32

// ---------------------------------------------------------------------------
// helpers
// ---------------------------------------------------------------------------
__device__ __forceinline__ uint32_t smem_u32(const void* p) {
    uint32_t a;
    asm("{ .reg .u64 t; cvta.to.shared.u64 t, %1; cvt.u32.u64 %0, t; }" : "=r"(a) : "l"(p));
    return a;
}

#define CP16(dst_u32, src_ptr) \
    asm volatile("cp.async.cg.shared.global [%0], [%1], 16;" :: "r"(dst_u32), "l"(src_ptr))
#define CP_COMMIT()  asm volatile("cp.async.commit_group;" ::: "memory")
#define CP_WAITG(n)  asm volatile("cp.async.wait_group %0;" :: "n"(n) : "memory")

#define LDSM_X4(r0, r1, r2, r3, addr) \
    asm volatile("ldmatrix.sync.aligned.m8n8.x4.shared.b16 {%0,%1,%2,%3}, [%4];" \
                 : "=r"(r0), "=r"(r1), "=r"(r2), "=r"(r3) : "r"(addr))

__device__ __forceinline__ void mma16816(float* c, const uint32_t* a, const uint32_t* b) {
    asm volatile(
        "mma.sync.aligned.m16n8k16.row.col.f32.bf16.bf16.f32 "
        "{%0,%1,%2,%3}, {%4,%5,%6,%7}, {%8,%9}, {%0,%1,%2,%3};"
        : "+f"(c[0]), "+f"(c[1]), "+f"(c[2]), "+f"(c[3])
        : "r"(a[0]), "r"(a[1]), "r"(a[2]), "r"(a[3]), "r"(b[0]), "r"(b[1]));
}

// ---------------------------------------------------------------------------
// Hi/lo splitters -> physical [hi(512) | lo(512)] rows of KA=1024.
// Logical GEMM K expansion happens via chunk remapping in gemm_hmma.
// ---------------------------------------------------------------------------
__device__ __forceinline__ void split_core(const float* __restrict__ in, int idx,
                                           int& r, int& c, uint2& H, uint2& L)
{
    r = idx >> 7;
    c = (idx & 127) << 2;
    float4 v = *reinterpret_cast<const float4*>(in + (size_t)r * CC + c);
    float f[4] = {v.x, v.y, v.z, v.w};
    uint32_t h[2], l[2];
    #pragma unroll
    for (int i = 0; i < 2; i++) {
        __nv_bfloat16 h0 = __float2bfloat16(f[2*i]);
        __nv_bfloat16 h1 = __float2bfloat16(f[2*i + 1]);
        __nv_bfloat16 l0 = __float2bfloat16(f[2*i]     - __bfloat162float(h0));
        __nv_bfloat16 l1 = __float2bfloat16(f[2*i + 1] - __bfloat162float(h1));
        h[i] = (uint32_t)__bfloat16_as_ushort(h0) | ((uint32_t)__bfloat16_as_ushort(h1) << 16);
        l[i] = (uint32_t)__bfloat16_as_ushort(l0) | ((uint32_t)__bfloat16_as_ushort(l1) << 16);
    }
    H = make_uint2(h[0], h[1]);
    L = make_uint2(l[0], l[1]);
}

__global__ void split2(const float* __restrict__ in, __nv_bfloat16* __restrict__ out, int rows)
{
    int idx = blockIdx.x * 256 + threadIdx.x;
    if (idx >= rows * 128) return;
    int r, c; uint2 H, L;
    split_core(in, idx, r, c, H, L);
    size_t base = (size_t)r * KA;
    *reinterpret_cast<uint2*>(out + base + c)       = H;
    *reinterpret_cast<uint2*>(out + base + 512 + c) = L;
}

__global__ void split2_w4(const float* __restrict__ Wq, const float* __restrict__ Wk,
                          const float* __restrict__ Wv, const float* __restrict__ Wp,
                          __nv_bfloat16* __restrict__ Bq, __nv_bfloat16* __restrict__ Bo)
{
    const int which = blockIdx.y;
    const float* src = (which == 0) ? Wq : (which == 1) ? Wk : (which == 2) ? Wv : Wp;
    __nv_bfloat16* dst = (which == 0) ? Bq
                       : (which == 1) ? Bq + (size_t)512 * KA
                       : (which == 2) ? Bq + (size_t)1024 * KA
                       : Bo;
    int idx = blockIdx.x * 256 + threadIdx.x;
    if (idx >= CC * 128) return;
    int r, c; uint2 H, L;
    split_core(src, idx, r, c, H, L);
    size_t base = (size_t)r * KA;
    *reinterpret_cast<uint2*>(dst + base + c)       = H;
    *reinterpret_cast<uint2*>(dst + base + 512 + c) = L;
}

// ---------------------------------------------------------------------------
// HMMA GEMM, logical K=1536 over physical [hi|lo] (KA=1024):
//   A chunks: kt 0-15 hi, 16-31 lo, 32-47 hi  -> ka = kt<32 ? kt : kt-32
//   B chunks: kt 0-15 hi, 16-31 hi, 32-47 lo  -> kb = kt<16 ? kt : kt-16
// BM=128: 2 CTAs/SM (QKV).  BM=64: 3 CTAs/SM (out proj, one full wave).
// 4-stage cp.async, ldmatrix, single barrier per iteration.
// ---------------------------------------------------------------------------
#define BK      32
#define PAD     40
#define STAGES  4
#define NKCH    (KLOG / BK)            // 48

template<int BM>
__global__ void __launch_bounds__(256, BM == 128 ? 2 : 3)
gemm_hmma(const __nv_bfloat16* __restrict__ Ag,
          const __nv_bfloat16* __restrict__ Bg,
          float* __restrict__ C, int ldc, const float* __restrict__ bias)
{
    constexpr int MI      = BM / 32;
    constexpr int TILEA   = BM * PAD;
    constexpr int TILEB   = 128 * PAD;

    extern __shared__ __align__(16) char smem[];
    const uint32_t sbase = smem_u32(smem);

    const int tid  = threadIdx.x;
    const int wid  = tid >> 5;
    const int lane = tid & 31;
    const int g    = lane >> 2;
    const int tig  = lane & 3;

    const int bm = blockIdx.y * BM;
    const int bn = blockIdx.x * 128;
    const int wm = (wid & 1) * (BM / 2);
    const int wn = (wid >> 1) * 32;

    auto load_stage = [&](int kt, int s) {
        const int ka = (kt < 32) ? kt : kt - 32;
        const int kb = (kt < 16) ? kt : kt - 16;
        const uint32_t abase = sbase + (uint32_t)(s * TILEA) * 2;
        const uint32_t bbase = sbase + (uint32_t)(STAGES * TILEA + s * TILEB) * 2;
        if constexpr (BM == 128) {
            const int r0 = tid >> 1;
            const int c0 = (tid & 1) * 16;
            const __nv_bfloat16* ap = Ag + (size_t)(bm + r0) * KA + ka * BK + c0;
            const uint32_t aoff = abase + (uint32_t)(r0 * PAD + c0) * 2;
            CP16(aoff,      ap);
            CP16(aoff + 16, ap + 8);
        } else {
            const int r0 = tid >> 2;
            const int c0 = (tid & 3) * 8;
            const __nv_bfloat16* ap = Ag + (size_t)(bm + r0) * KA + ka * BK + c0;
            CP16(abase + (uint32_t)(r0 * PAD + c0) * 2, ap);
        }
        {
            const int r0 = tid >> 1;
            const int c0 = (tid & 1) * 16;
            const __nv_bfloat16* bp = Bg + (size_t)(bn + r0) * KA + kb * BK + c0;
            const uint32_t boff = bbase + (uint32_t)(r0 * PAD + c0) * 2;
            CP16(boff,      bp);
            CP16(boff + 16, bp + 8);
        }
    };

    const uint32_t a_off = (uint32_t)((wm + (lane & 15)) * PAD + (lane >> 4) * 8) * 2;
    const uint32_t b_off = (uint32_t)((wn + (lane >> 4) * 8 + (lane & 7)) * PAD
                                      + ((lane >> 3) & 1) * 8) * 2;

    float acc[MI][4][4] = {};

    load_stage(0, 0); CP_COMMIT();
    load_stage(1, 1); CP_COMMIT();
    load_stage(2, 2); CP_COMMIT();

    for (int kt = 0; kt < NKCH; kt++) {
        CP_WAITG(2);
        __syncthreads();

        const int nk = kt + STAGES - 1;
        if (nk < NKCH) load_stage(nk, nk & 3);
        CP_COMMIT();

        const uint32_t at = sbase + (uint32_t)((kt & 3) * TILEA) * 2 + a_off;
        const uint32_t bt = sbase + (uint32_t)(STAGES * TILEA + (kt & 3) * TILEB) * 2 + b_off;

        #pragma unroll
        for (int kk = 0; kk < BK; kk += 16) {
            uint32_t af[MI][4], bf[4][2];
            #pragma unroll
            for (int mi = 0; mi < MI; mi++)
                LDSM_X4(af[mi][0], af[mi][1], af[mi][2], af[mi][3],
                        at + (uint32_t)(mi * 16 * PAD + kk) * 2);
            #pragma unroll
            for (int np = 0; np < 2; np++)
                LDSM_X4(bf[2*np][0], bf[2*np][1], bf[2*np+1][0], bf[2*np+1][1],
                        bt + (uint32_t)(np * 16 * PAD + kk) * 2);
            #pragma unroll
            for (int mi = 0; mi < MI; mi++)
                #pragma unroll
                for (int ni = 0; ni < 4; ni++)
                    mma16816(acc[mi][ni], af[mi], bf[ni]);
        }
    }

    #pragma unroll
    for (int mi = 0; mi < MI; mi++) {
        const int row0 = bm + wm + mi * 16 + g;
        #pragma unroll
        for (int ni = 0; ni < 4; ni++) {
            const int col = bn + wn + ni * 8 + tig * 2;
            float b0 = 0.f, b1 = 0.f;
            if (bias) { b0 = bias[col]; b1 = bias[col + 1]; }
            float2 lo = make_float2(acc[mi][ni][0] + b0, acc[mi][ni][1] + b1);
            float2 hi = make_float2(acc[mi][ni][2] + b0, acc[mi][ni][3] + b1);
            *reinterpret_cast<float2*>(C + (size_t)row0 * ldc + col)       = lo;
            *reinterpret_cast<float2*>(C + (size_t)(row0 + 8) * ldc + col) = hi;
        }
    }
}

// ---------------------------------------------------------------------------
// Tiled sparse triplane attention — R12 structure restored (SROW=64 exchange,
// smem grow table), only delta: compact [hi|lo] output write (2 stores).
// Key-major warps, V-from-L2, K prefetch.  3 CTAs/SM.
// ---------------------------------------------------------------------------
#define KROW 68         // K buffer row stride (floats)
#define SROW 64         // shared-region row stride (floats)

__global__ void __launch_bounds__(256, 3)
attn_tile(const float* __restrict__ qkv, __nv_bfloat16* __restrict__ Aout)
{
    extern __shared__ __align__(16) float sm[];
    float* Ks    = sm;                         // [256][KROW]  K only
    float* Sh    = sm + 256 * KROW;            // [16][SROW]   Qh/scores/probs/oex
    int*   growS = (int*)(Sh + 16 * SROW);     // [256]
    const uint32_t ks_base = smem_u32(Ks);
    const uint32_t sh_base = smem_u32(Sh);

    const int x  = blockIdx.x;                 // 0..383
    const int b  = x / 192;
    const int r0 = x % 192;
    const int p  = r0 >> 6;
    const int t0 = r0 & 63;
    const int i0 = (t0 >> 3) << 2;
    const int j0 = (t0 & 7) << 2;

    const int tid  = threadIdx.x;
    const int wid  = tid >> 5;
    const int lane = tid & 31;

    const float* Bq = qkv + (size_t)b * NN * NQKV;

    {
        const int rr = tid;
        const int rl = rr & 127;
        int gr;
        if (p == 0)
            gr = (rr < 128) ? (1024 + 32 * i0 + rl) : (2048 + 32 * j0 + rl);
        else if (p == 1)
            gr = (rr < 128) ? (32 * i0 + rl)
                            : (2048 + 32 * (rl & 31) + j0 + (rl >> 5));
        else
            gr = (rr < 128) ? (32 * (rl & 31) + i0 + (rl >> 5))
                            : (1024 + 32 * (rl & 31) + j0 + (rl >> 5));
        growS[rr] = gr;
    }
    __syncthreads();

    const bool g0     = (wid < 4);
    const int  grp    = g0 ? wid : (wid - 4);
    const int  krow0  = g0 ? (grp * 32) : (128 + grp * 32);
    const int  c4t    = tid & 15;
    const int  myGrow = growS[krow0 + lane];

    auto load_K = [&](int h) {
        #pragma unroll
        for (int it = 0; it < 16; it++) {
            const int rr = it * 16 + (tid >> 4);
            const float* src = Bq + (size_t)growS[rr] * NQKV + 512 + h * DD + c4t * 4;
            CP16(ks_base + (uint32_t)(rr * KROW + c4t * 4) * 4, src);
        }
    };

    load_K(0); CP_COMMIT();

    for (int h = 0; h < HH; h++) {
        {
            const int qr = tid >> 4;
            const int n  = (p << 10) + (i0 + (qr >> 2)) * 32 + (j0 + (qr & 3));
            CP16(sh_base + (uint32_t)(qr * SROW + c4t * 4) * 4,
                 Bq + (size_t)n * NQKV + h * DD + c4t * 4);
        }
        CP_COMMIT(); CP_WAITG(0);
        __syncthreads();                               // S1

        float s[4] = {0.f, 0.f, 0.f, 0.f};
        {
            const float4* Krow = reinterpret_cast<const float4*>(Ks + (krow0 + lane) * KROW);
            #pragma unroll
            for (int d4 = 0; d4 < 16; d4++) {
                const float4 kv = Krow[d4];
                #pragma unroll
                for (int qq = 0; qq < 4; qq++) {
                    const int q = g0 ? (grp * 4 + qq) : (qq * 4 + grp);
                    const float4 qv = *reinterpret_cast<const float4*>(Sh + q * SROW + d4 * 4);
                    s[qq] += qv.x * kv.x + qv.y * kv.y + qv.z * kv.z + qv.w * kv.w;
                }
            }
        }
        __syncthreads();                               // S2

        if (h + 1 < HH) load_K(h + 1);
        CP_COMMIT();

        {
            const int slot = g0 ? lane : (32 + lane);
            #pragma unroll
            for (int qq = 0; qq < 4; qq++) {
                const int q = g0 ? (grp * 4 + qq) : (qq * 4 + grp);
                Sh[q * SROW + slot] = s[qq] * 0.125f;
            }
        }
        __syncthreads();                               // S3

        #pragma unroll
        for (int qq = 0; qq < 2; qq++) {
            const int q = wid * 2 + qq;
            float s0 = Sh[q * SROW + lane];
            float s1 = Sh[q * SROW + lane + 32];
            float m = fmaxf(s0, s1);
            #pragma unroll
            for (int off = 16; off; off >>= 1)
                m = fmaxf(m, __shfl_xor_sync(0xffffffffu, m, off));
            const float e0 = __expf(s0 - m), e1 = __expf(s1 - m);
            float su = e0 + e1;
            #pragma unroll
            for (int off = 16; off; off >>= 1)
                su += __shfl_xor_sync(0xffffffffu, su, off);
            const float inv = 1.0f / su;
            Sh[q * SROW + lane]      = e0 * inv;
            Sh[q * SROW + lane + 32] = e1 * inv;
        }
        __syncthreads();                               // S4

        float o[4][2] = {};
        {
            const int slot0 = g0 ? 0 : 32;
            #pragma unroll
            for (int t = 0; t < 32; t++) {
                const int gr = __shfl_sync(0xffffffffu, myGrow, t);
                const float2 v2 = *reinterpret_cast<const float2*>(
                    Bq + (size_t)gr * NQKV + 1024 + h * DD + 2 * lane);
                #pragma unroll
                for (int qq = 0; qq < 4; qq++) {
                    const int q = g0 ? (grp * 4 + qq) : (qq * 4 + grp);
                    const float pt = Sh[q * SROW + slot0 + t];
                    o[qq][0] += pt * v2.x;
                    o[qq][1] += pt * v2.y;
                }
            }
        }
        __syncthreads();                               // S5

        if (g0) {
            #pragma unroll
            for (int qq = 0; qq < 4; qq++) {
                const int q = grp * 4 + qq;
                *reinterpret_cast<float2*>(Sh + q * SROW + 2 * lane) =
                    make_float2(o[qq][0], o[qq][1]);
            }
        }
        __syncthreads();                               // S6
        if (!g0) {
            #pragma unroll
            for (int qq = 0; qq < 4; qq++) {
                const int q = qq * 4 + grp;
                float2 v = *reinterpret_cast<float2*>(Sh + q * SROW + 2 * lane);
                v.x += o[qq][0]; v.y += o[qq][1];
                *reinterpret_cast<float2*>(Sh + q * SROW + 2 * lane) = v;
            }
        }
        __syncthreads();                               // S7

        #pragma unroll
        for (int qq = 0; qq < 2; qq++) {
            const int q = wid * 2 + qq;
            const float2 ov = *reinterpret_cast<const float2*>(Sh + q * SROW + 2 * lane);
            const int n = (p << 10) + (i0 + (q >> 2)) * 32 + (j0 + (q & 3));
            const size_t ab = (size_t)(b * NN + n) * KA + h * DD;
            const __nv_bfloat16 h0 = __float2bfloat16(ov.x);
            const __nv_bfloat16 l0 = __float2bfloat16(ov.x - __bfloat162float(h0));
            const __nv_bfloat16 h1 = __float2bfloat16(ov.y);
            const __nv_bfloat16 l1 = __float2bfloat16(ov.y - __bfloat162float(h1));
            __nv_bfloat162 Hp; Hp.x = h0; Hp.y = h1;
            __nv_bfloat162 Lp; Lp.x = l0; Lp.y = l1;
            *reinterpret_cast<__nv_bfloat162*>(&Aout[ab + 2 * lane])       = Hp;
            *reinterpret_cast<__nv_bfloat162*>(&Aout[ab + 512 + 2 * lane]) = Lp;
        }
        __syncthreads();                               // S8
    }
}

// ---------------------------------------------------------------------------
// Host side
// ---------------------------------------------------------------------------
extern "C" void kernel_launch(void* const* d_in, const int* in_sizes, int n_in,
                              void* d_out, int out_size)
{
    const float* x  = (const float*)d_in[0];
    const float* Wq = (const float*)d_in[1];
    const float* Wk = (const float*)d_in[2];
    const float* Wv = (const float*)d_in[3];
    const float* Wp = (const float*)d_in[4];
    const float* bp = (const float*)d_in[5];
    float* out = (float*)d_out;

    __nv_bfloat16 *A, *Bq, *Bo;
    float *qkv;
    cudaGetSymbolAddress((void**)&A,   g_A);
    cudaGetSymbolAddress((void**)&Bq,  g_Bqkv);
    cudaGetSymbolAddress((void**)&Bo,  g_Bout);
    cudaGetSymbolAddress((void**)&qkv, g_qkv);

    constexpr int SMEM_G128 = STAGES * (128 + 128) * PAD * 2;         // 81920
    constexpr int SMEM_G64  = STAGES * (64 + 128) * PAD * 2;          // 61440
    constexpr int SMEM_A    = (256 * KROW + 16 * SROW) * 4 + 256 * 4; // 74752
    static bool s_attr = false;
    if (!s_attr) {
        cudaFuncSetAttribute(gemm_hmma<128>, cudaFuncAttributeMaxDynamicSharedMemorySize, SMEM_G128);
        cudaFuncSetAttribute(gemm_hmma<64>,  cudaFuncAttributeMaxDynamicSharedMemorySize, SMEM_G64);
        cudaFuncSetAttribute(attn_tile,      cudaFuncAttributeMaxDynamicSharedMemorySize, SMEM_A);
        s_attr = true;
    }

    // 1) hi/lo splits (compact [hi|lo] storage)
    split2<<<(MM * 128 + 255) / 256, 256>>>(x, A, MM);
    split2_w4<<<dim3((CC * 128 + 255) / 256, 4), 256>>>(Wq, Wk, Wv, Wp, Bq, Bo);

    // 2) fused QKV projection (logical K=1536 via chunk remap)
    gemm_hmma<128><<<dim3(NQKV / 128, MM / 128), 256, SMEM_G128>>>(A, Bq, qkv, NQKV, nullptr);

    // 3) tiled sparse attention (R12 structure, compact split output)
    attn_tile<<<NB * 3 * 64, 256, SMEM_A>>>(qkv, A);

    // 4) output projection (BM=64: one full wave)
    gemm_hmma<64><<<dim3(CC / 128, MM / 64), 256, SMEM_G64>>>(A, Bo, out, CC, bp);
}